// round 8
// baseline (speedup 1.0000x reference)
#include <cuda_runtime.h>

#define FULLMASK 0xffffffffu

__device__ __forceinline__ float shx(float v, int m) { return __shfl_xor_sync(FULLMASK, v, m); }

// Packed fp32x2 math (Blackwell FFMA2 path — only reachable via PTX f32x2).
// Used ONLY in the encoding loop where packed pairs are natural and reused.
__device__ __forceinline__ void mul2(float& d0, float& d1, float a0, float a1,
                                     float b0, float b1) {
    asm("{\n\t.reg .b64 A,B,D;\n\t"
        "mov.b64 A, {%2,%3};\n\t"
        "mov.b64 B, {%4,%5};\n\t"
        "mul.rn.f32x2 D, A, B;\n\t"
        "mov.b64 {%0,%1}, D;\n\t}"
        : "=f"(d0), "=f"(d1) : "f"(a0), "f"(a1), "f"(b0), "f"(b1));
}
__device__ __forceinline__ void fma2(float& d0, float& d1, float a0, float a1,
                                     float b0, float b1, float c0, float c1) {
    asm("{\n\t.reg .b64 A,B,C,D;\n\t"
        "mov.b64 A, {%2,%3};\n\t"
        "mov.b64 B, {%4,%5};\n\t"
        "mov.b64 C, {%6,%7};\n\t"
        "fma.rn.f32x2 D, A, B, C;\n\t"
        "mov.b64 {%0,%1}, D;\n\t}"
        : "=f"(d0), "=f"(d1) : "f"(a0), "f"(a1), "f"(b0), "f"(b1), "f"(c0), "f"(c1));
}

// Layout: HALF-WARP per batch element, 16 amplitudes per lane.
// sub-lane sl = lane & 15 (bits L3..L0), register index r (bits R3..R0).
// Qubit -> bit mapping (parity trick: odd qubits live in registers):
//   q0->L3  q2->L2  q4->L1  q6->L0     (lane bits)
//   q1->R3  q3->R2  q5->R1  q7->R0     (register bits)
// All shuffle masks <= 8 => shuffles never cross the half-warp boundary.

// ---- RY on lane bit LB with PRE-CNOT(control = reg bit 0) fused (ring-closing CX(7,0)) ----
template<int LB>
__device__ __forceinline__ void ryl2_cx(float a[16], float c, float s, int lane) {
    const float sg = ((lane >> LB) & 1) ? s : -s;
#pragma unroll
    for (int r = 0; r < 16; r += 2) {
        float p0 = shx(a[r],     1 << LB);   // r even: control clear
        float p1 = shx(a[r + 1], 1 << LB);   // r+1 odd: control set -> pre-swap own/partner
        float t0, t1;
        mul2(t0, t1, a[r], p1, c, c);
        fma2(t0, t1, p0, a[r + 1], sg, sg, t0, t1);
        a[r] = t0; a[r + 1] = t1;
    }
}

// ---- RY on lane bit LB with POST-CNOT(control = reg bit CB, target = same lane bit) fused ----
template<int LB, int CB>
__device__ __forceinline__ void ryl2_post(float a[16], float c, float s, int lane) {
    const float sg = ((lane >> LB) & 1) ? s : -s;
    const float nsg = -sg;
#pragma unroll
    for (int r = 0; r < 16; r += 2) {
        float p0 = shx(a[r],     1 << LB);
        float p1 = shx(a[r + 1], 1 << LB);
        float t0, t1;
        if (r & (1 << CB)) {          // CB >= 1 so pair is homogeneous
            mul2(t0, t1, p0, p1, c, c);
            fma2(t0, t1, a[r], a[r + 1], nsg, nsg, t0, t1);
        } else {
            mul2(t0, t1, a[r], a[r + 1], c, c);
            fma2(t0, t1, p0, p1, sg, sg, t0, t1);
        }
        a[r] = t0; a[r + 1] = t1;
    }
}

// ---- RY on reg bit BT with POST-CNOT(control = lane bit LC, target = same reg bit) fused ----
template<int BT, int LC>
__device__ __forceinline__ void ryr2_cx(float a[16], float c, float s, int lane) {
    const bool p = (lane >> LC) & 1;
    const float A = p ?  s : c;
    const float B = p ?  c : -s;
    const float C = p ?  c : s;
    const float D = p ? -s : c;
#pragma unroll
    for (int j = 0; j < 4; ++j) {
        const int k0 = 2 * j, k1 = 2 * j + 1;
        const int pp = ((k0 >> BT) << (BT + 1)) | (k0 & ((1 << BT) - 1));
        const int qq = ((k1 >> BT) << (BT + 1)) | (k1 & ((1 << BT) - 1));
        const int pm = pp | (1 << BT), qm = qq | (1 << BT);
        float l0, l1, h0, h1;
        mul2(l0, l1, a[pp], a[qq], A, A);
        fma2(l0, l1, a[pm], a[qm], B, B, l0, l1);
        mul2(h0, h1, a[pp], a[qq], C, C);
        fma2(h0, h1, a[pm], a[qm], D, D, h0, h1);
        a[pp] = l0; a[qq] = l1; a[pm] = h0; a[qm] = h1;
    }
}

// ---- CNOT: control reg bit BC, target lane bit LT (8 shuffles) ----
template<int BC, int LT>
__device__ __forceinline__ void crl(float a[16]) {
#pragma unroll
    for (int r = 0; r < 16; ++r) {
        if (r & (1 << BC)) a[r] = shx(a[r], 1 << LT);
    }
}

// ======= CRX gates (scalar): [[c, -i s],[-i s, c]] on control==1 subspace =======
template<int LC, int BT>
__device__ __forceinline__ void crx_lr_r2c(float ar[16], float ai[16], float c, float s, int lane) {
    const bool p = (lane >> LC) & 1;
    const float ce  = p ? c  : 1.0f;
    const float nse = p ? -s : 0.0f;
#pragma unroll
    for (int r = 0; r < 16; ++r) {
        if (!(r & (1 << BT))) {
            const int r1 = r | (1 << BT);
            ai[r]  = nse * ar[r1];
            ai[r1] = nse * ar[r];
            ar[r]  = ce * ar[r];
            ar[r1] = ce * ar[r1];
        }
    }
}

template<int LC, int BT>
__device__ __forceinline__ void crx_lr(float ar[16], float ai[16], float c, float s, int lane) {
    const bool p = (lane >> LC) & 1;
    const float ce = p ? c : 1.0f;
    const float se = p ? s : 0.0f;
#pragma unroll
    for (int r = 0; r < 16; ++r) {
        if (!(r & (1 << BT))) {
            const int r1 = r | (1 << BT);
            float a0r = ar[r], a0i = ai[r], a1r = ar[r1], a1i = ai[r1];
            ar[r]  = fmaf( se, a1i, ce * a0r);
            ai[r]  = fmaf(-se, a1r, ce * a0i);
            ar[r1] = fmaf( se, a0i, ce * a1r);
            ai[r1] = fmaf(-se, a0r, ce * a1i);
        }
    }
}

template<int BC, int LT>
__device__ __forceinline__ void crx_rl(float ar[16], float ai[16], float c, float s) {
#pragma unroll
    for (int r = 0; r < 16; ++r) {
        if (r & (1 << BC)) {
            float pr = shx(ar[r], 1 << LT);
            float pi = shx(ai[r], 1 << LT);
            float nr = fmaf( s, pi, c * ar[r]);
            float ni = fmaf(-s, pr, c * ai[r]);
            ar[r] = nr; ai[r] = ni;
        }
    }
}

template<int BC, int BT>
__device__ __forceinline__ void crx_rr(float ar[16], float ai[16], float c, float s) {
#pragma unroll
    for (int r = 0; r < 16; ++r) {
        if ((r & (1 << BC)) && !(r & (1 << BT))) {
            const int r1 = r | (1 << BT);
            float a0r = ar[r], a0i = ai[r], a1r = ar[r1], a1i = ai[r1];
            ar[r]  = fmaf( s, a1i, c * a0r);
            ai[r]  = fmaf(-s, a1r, c * a0i);
            ar[r1] = fmaf( s, a0i, c * a1r);
            ai[r1] = fmaf(-s, a0r, c * a1i);
        }
    }
}

// ---------------- U3 on a reg bit (scalar, no shuffles); exploits u00i == 0 ----------------
template<int BT>
__device__ __forceinline__ void u3_reg(float ar[16], float ai[16],
    float u00r, float u01r, float u01i,
    float u10r, float u10i, float u11r, float u11i) {
#pragma unroll
    for (int r = 0; r < 16; ++r) {
        if (!(r & (1 << BT))) {
            const int r1 = r | (1 << BT);
            float a0r = ar[r], a0i = ai[r], a1r = ar[r1], a1i = ai[r1];
            ar[r]  = fmaf(-u01i, a1i, fmaf(u01r, a1r, u00r * a0r));
            ai[r]  = fmaf( u01i, a1r, fmaf(u01r, a1i, u00r * a0i));
            ar[r1] = fmaf(-u11i, a1i, fmaf(u11r, a1r, fmaf(-u10i, a0i, u10r * a0r)));
            ai[r1] = fmaf( u11i, a1r, fmaf(u11r, a1i, fmaf( u10i, a0r, u10r * a0i)));
        }
    }
}

__device__ __forceinline__ void u3_coeffs(const float* __restrict__ p3,
    float& u00r, float& u01r, float& u01i,
    float& u10r, float& u10i, float& u11r, float& u11i) {
    const float th = p3[0], ph = p3[1], lm = p3[2];
    float st, ct;   __sincosf(0.5f * th, &st, &ct);
    float sl, cl;   __sincosf(lm, &sl, &cl);
    float sp, cp;   __sincosf(ph, &sp, &cp);
    float spl, cpl; __sincosf(ph + lm, &spl, &cpl);
    u00r = ct;
    u01r = -cl * st;  u01i = -sl * st;
    u10r =  cp * st;  u10i =  sp * st;
    u11r = cpl * ct;  u11i = spl * ct;
}

// ==================================================================================
__global__ void __launch_bounds__(256, 5) qcnn_kernel(
    const float* __restrict__ x,
    const float* __restrict__ crx_theta,
    const float* __restrict__ u3p,
    const float* __restrict__ w1,
    const float* __restrict__ b1,
    const float* __restrict__ w2,
    const float* __restrict__ b2,
    float* __restrict__ out, int nB)
{
    const int warp = (blockIdx.x * blockDim.x + threadIdx.x) >> 5;
    if (2 * warp >= nB) return;
    const int lane = threadIdx.x & 31;
    const int hl = lane >> 4;
    const int e  = 2 * warp + hl;
    const int el = (e < nB) ? e : (nB - 1);
    const int sl = lane & 15;

    // ---- per-element RY angles (reused across all 4 cycles) ----
    float c8[8], s8[8];
    {
        const float4 x0 = reinterpret_cast<const float4*>(x + el * 8)[0];
        const float4 x1 = reinterpret_cast<const float4*>(x + el * 8)[1];
        float xs[8] = {x0.x, x0.y, x0.z, x0.w, x1.x, x1.y, x1.z, x1.w};
#pragma unroll
        for (int q = 0; q < 8; ++q) __sincosf(0.5f * xs[q], &s8[q], &c8[q]);
    }

    // ---- cycle 1: RY layer on |0..0> + CNOT ring (minus (q7,q0)) in closed form ----
    float a[16];
    {
        const bool L3 = sl & 8, L2 = sl & 4, L1 = sl & 2, L0 = sl & 1;
        const float P0  = L3 ? s8[0] : c8[0];
        const float w3a = (L3 ? s8[1] : c8[1]) * (L2 ? s8[2] : c8[2]);   // R3 = 0
        const float w3b = (L3 ? c8[1] : s8[1]) * (L2 ? c8[2] : s8[2]);   // R3 = 1
        const float w2a = (L2 ? s8[3] : c8[3]) * (L1 ? s8[4] : c8[4]);
        const float w2b = (L2 ? c8[3] : s8[3]) * (L1 ? c8[4] : s8[4]);
        const float w1a = (L1 ? s8[5] : c8[5]) * (L0 ? s8[6] : c8[6]);
        const float w1b = (L1 ? c8[5] : s8[5]) * (L0 ? c8[6] : s8[6]);
        const float w0a = L0 ? s8[7] : c8[7];
        const float w0b = L0 ? c8[7] : s8[7];
        const float A0 = P0 * w3a, A1 = P0 * w3b;
        const float B00 = A0 * w2a, B01 = A0 * w2b, B10 = A1 * w2a, B11 = A1 * w2b;
        const float C0 = B00 * w1a, C1 = B00 * w1b, C2 = B01 * w1a, C3 = B01 * w1b;
        const float C4 = B10 * w1a, C5 = B10 * w1b, C6 = B11 * w1a, C7 = B11 * w1b;
        a[0]  = C0 * w0a;  a[1]  = C0 * w0b;  a[2]  = C1 * w0a;  a[3]  = C1 * w0b;
        a[4]  = C2 * w0a;  a[5]  = C2 * w0b;  a[6]  = C3 * w0a;  a[7]  = C3 * w0b;
        a[8]  = C4 * w0a;  a[9]  = C4 * w0b;  a[10] = C5 * w0a;  a[11] = C5 * w0b;
        a[12] = C6 * w0a;  a[13] = C6 * w0b;  a[14] = C7 * w0a;  a[15] = C7 * w0b;
    }

    // ---- cycles 2..4: RY layer with all ring CNOTs fused in ----
#pragma unroll 1
    for (int cyc = 0; cyc < 3; ++cyc) {
        ryl2_cx<3>(a, c8[0], s8[0], lane);       // RY q0, pre-CX(7,0) ctrl R0
        ryr2_cx<3, 3>(a, c8[1], s8[1], lane);    // RY q1 (R3), post-CX ctrl q0 (L3)
        ryl2_post<2, 3>(a, c8[2], s8[2], lane);  // RY q2 (L2), post-CX ctrl q1 (R3)
        ryr2_cx<2, 2>(a, c8[3], s8[3], lane);    // RY q3 (R2), post-CX ctrl q2 (L2)
        ryl2_post<1, 2>(a, c8[4], s8[4], lane);  // RY q4 (L1), post-CX ctrl q3 (R2)
        ryr2_cx<1, 1>(a, c8[5], s8[5], lane);    // RY q5 (R1), post-CX ctrl q4 (L1)
        ryl2_post<0, 1>(a, c8[6], s8[6], lane);  // RY q6 (L0), post-CX ctrl q5 (R1)
        ryr2_cx<0, 0>(a, c8[7], s8[7], lane);    // RY q7 (R0), post-CX ctrl q6 (L0)
    }
    crl<0, 3>(a);                                // final pending CX(7,0)

    // ================= final (complex) stage, scalar =================
    float* ar = a;
    float ai[16];

    // ---- layer 0 CRX ----
    {
        float s0, c0;
        __sincosf(0.5f * crx_theta[0], &s0, &c0);
        crx_lr_r2c<3, 3>(ar, ai, c0, s0, lane);  // (q0,q1) real -> complex
        crx_lr<2, 2>(ar, ai, c0, s0, lane);      // (q2,q3)
        crx_lr<1, 1>(ar, ai, c0, s0, lane);      // (q4,q5)
        crx_lr<0, 0>(ar, ai, c0, s0, lane);      // (q6,q7)
        crx_rl<3, 2>(ar, ai, c0, s0);            // (q1,q2)
        crx_rl<2, 1>(ar, ai, c0, s0);            // (q3,q4)
        crx_rl<1, 0>(ar, ai, c0, s0);            // (q5,q6)
    }
    // ---- layer 0 U3 on qubits [1,3,5,7] (register-local) ----
    {
        float u00r,u01r,u01i,u10r,u10i,u11r,u11i;
        u3_coeffs(u3p, u00r,u01r,u01i,u10r,u10i,u11r,u11i);
        u3_reg<3>(ar, ai, u00r,u01r,u01i,u10r,u10i,u11r,u11i);  // q1
        u3_reg<2>(ar, ai, u00r,u01r,u01i,u10r,u10i,u11r,u11i);  // q3
        u3_reg<1>(ar, ai, u00r,u01r,u01i,u10r,u10i,u11r,u11i);  // q5
        u3_reg<0>(ar, ai, u00r,u01r,u01i,u10r,u10i,u11r,u11i);  // q7
    }
    // ---- layer 1 CRX on [1,3,5,7]: (1,3)(5,7) then (3,5) — register-local ----
    {
        float s1, c1;
        __sincosf(0.5f * crx_theta[1], &s1, &c1);
        crx_rr<3, 2>(ar, ai, c1, s1);    // (q1,q3)
        crx_rr<1, 0>(ar, ai, c1, s1);    // (q5,q7)
        crx_rr<2, 1>(ar, ai, c1, s1);    // (q3,q5)
    }

    // ---- layer 1 U3 on q3,q7 folded into the measurement:
    //      <Z after U3> = <M> with M = U† Z U = [[aM, b],[conj(b), -aM]].
    float aM, bMr, bMi;
    {
        float u00r,u01r,u01i,u10r,u10i,u11r,u11i;
        u3_coeffs(u3p + 3, u00r,u01r,u01i,u10r,u10i,u11r,u11i);
        aM  = u00r * u00r - (u10r * u10r + u10i * u10i);
        bMr = 2.0f * (u00r * u01r - (u10r * u11r + u10i * u11i));
        bMi = 2.0f * (u00r * u01i - (u10r * u11i - u10i * u11r));
    }
    // f0 = <M on q3> (reg bit 2), f1 = <M on q7> (reg bit 0).
    float f0 = 0.0f, f1 = 0.0f;
#pragma unroll
    for (int qd = 0; qd < 4; ++qd) {
        const int r = ((qd >> 1) << 3) | ((qd & 1) << 1);   // 0, 2, 8, 10
        const int rA = r, rB = r | 1, rC = r | 4, rD = r | 5;
        const float mA = fmaf(ar[rA], ar[rA], ai[rA] * ai[rA]);
        const float mB = fmaf(ar[rB], ar[rB], ai[rB] * ai[rB]);
        const float mC = fmaf(ar[rC], ar[rC], ai[rC] * ai[rC]);
        const float mD = fmaf(ar[rD], ar[rD], ai[rD] * ai[rD]);
        // f0 pairs: (A,C), (B,D)
        {
            float wre = fmaf(ai[rA], ai[rC], ar[rA] * ar[rC]);
            float wim = fmaf(-ai[rA], ar[rC], ar[rA] * ai[rC]);
            f0 = fmaf(aM, mA - mC, f0);
            f0 = fmaf(bMr, wre, f0);
            f0 = fmaf(-bMi, wim, f0);
            wre = fmaf(ai[rB], ai[rD], ar[rB] * ar[rD]);
            wim = fmaf(-ai[rB], ar[rD], ar[rB] * ai[rD]);
            f0 = fmaf(aM, mB - mD, f0);
            f0 = fmaf(bMr, wre, f0);
            f0 = fmaf(-bMi, wim, f0);
        }
        // f1 pairs: (A,B), (C,D)
        {
            float wre = fmaf(ai[rA], ai[rB], ar[rA] * ar[rB]);
            float wim = fmaf(-ai[rA], ar[rB], ar[rA] * ai[rB]);
            f1 = fmaf(aM, mA - mB, f1);
            f1 = fmaf(bMr, wre, f1);
            f1 = fmaf(-bMi, wim, f1);
            wre = fmaf(ai[rC], ai[rD], ar[rC] * ar[rD]);
            wim = fmaf(-ai[rC], ar[rD], ar[rC] * ai[rD]);
            f1 = fmaf(aM, mC - mD, f1);
            f1 = fmaf(bMr, wre, f1);
            f1 = fmaf(-bMi, wim, f1);
        }
    }
#pragma unroll
    for (int m = 8; m >= 1; m >>= 1) {   // stays within half-warp
        f0 += shx(f0, m);
        f1 += shx(f1, m);
    }

    // ---- MLP head: sigmoid(tanh(f @ w1 + b1) @ w2 + b2), tanh spread over 10 lanes ----
    float contrib = 0.0f;
    if (sl < 10) {
        float h = tanhf(fmaf(f0, w1[sl], fmaf(f1, w1[10 + sl], b1[sl])));
        contrib = h * w2[sl];
    }
#pragma unroll
    for (int m = 8; m >= 1; m >>= 1) contrib += shx(contrib, m);
    if (sl == 0 && e < nB) {
        out[e] = 1.0f / (1.0f + __expf(-(contrib + b2[0])));
    }
}

extern "C" void kernel_launch(void* const* d_in, const int* in_sizes, int n_in,
                              void* d_out, int out_size) {
    const float* x         = (const float*)d_in[0];
    const float* crx_theta = (const float*)d_in[1];
    const float* u3_params = (const float*)d_in[2];
    const float* w1        = (const float*)d_in[3];
    const float* b1        = (const float*)d_in[4];
    const float* w2        = (const float*)d_in[5];
    const float* b2        = (const float*)d_in[6];
    float* out = (float*)d_out;

    const int nB = out_size;                  // (B, 1) output -> B batch elements
    const int threads = 256;                  // 8 warps/block, 2 elements per warp
    const int nWarps = (nB + 1) / 2;
    const int blocks = (nWarps * 32 + threads - 1) / threads;
    qcnn_kernel<<<blocks, threads>>>(x, crx_theta, u3_params, w1, b1, w2, b2, out, nB);
}

// round 11
// speedup vs baseline: 1.1630x; 1.1630x over previous
#include <cuda_runtime.h>

#define FULLMASK 0xffffffffu

__device__ __forceinline__ float shx(float v, int m) { return __shfl_xor_sync(FULLMASK, v, m); }

// Packed fp32x2 math (Blackwell FFMA2 path — only reachable via PTX f32x2).
// Used ONLY in the encoding loop where packed pairs are natural and reused.
__device__ __forceinline__ void mul2(float& d0, float& d1, float a0, float a1,
                                     float b0, float b1) {
    asm("{\n\t.reg .b64 A,B,D;\n\t"
        "mov.b64 A, {%2,%3};\n\t"
        "mov.b64 B, {%4,%5};\n\t"
        "mul.rn.f32x2 D, A, B;\n\t"
        "mov.b64 {%0,%1}, D;\n\t}"
        : "=f"(d0), "=f"(d1) : "f"(a0), "f"(a1), "f"(b0), "f"(b1));
}
__device__ __forceinline__ void fma2(float& d0, float& d1, float a0, float a1,
                                     float b0, float b1, float c0, float c1) {
    asm("{\n\t.reg .b64 A,B,C,D;\n\t"
        "mov.b64 A, {%2,%3};\n\t"
        "mov.b64 B, {%4,%5};\n\t"
        "mov.b64 C, {%6,%7};\n\t"
        "fma.rn.f32x2 D, A, B, C;\n\t"
        "mov.b64 {%0,%1}, D;\n\t}"
        : "=f"(d0), "=f"(d1) : "f"(a0), "f"(a1), "f"(b0), "f"(b1), "f"(c0), "f"(c1));
}

// Layout: HALF-WARP per batch element, 16 amplitudes per lane.
// sub-lane sl = lane & 15 (bits L3..L0), register index r (bits R3..R0).
// Qubit -> bit mapping (parity trick: odd qubits live in registers):
//   q0->L3  q2->L2  q4->L1  q6->L0     (lane bits)
//   q1->R3  q3->R2  q5->R1  q7->R0     (register bits)
// All shuffle masks <= 8 => shuffles never cross the half-warp boundary.

// ---- RY on lane bit LB with PRE-CNOT(control = reg bit 0) fused (ring-closing CX(7,0)) ----
template<int LB>
__device__ __forceinline__ void ryl2_cx(float a[16], float c, float s, int lane) {
    const float sg = ((lane >> LB) & 1) ? s : -s;
#pragma unroll
    for (int r = 0; r < 16; r += 2) {
        float p0 = shx(a[r],     1 << LB);   // r even: control clear
        float p1 = shx(a[r + 1], 1 << LB);   // r+1 odd: control set -> pre-swap own/partner
        float t0, t1;
        mul2(t0, t1, a[r], p1, c, c);
        fma2(t0, t1, p0, a[r + 1], sg, sg, t0, t1);
        a[r] = t0; a[r + 1] = t1;
    }
}

// ---- RY on lane bit LB with POST-CNOT(control = reg bit CB, target = same lane bit) fused ----
template<int LB, int CB>
__device__ __forceinline__ void ryl2_post(float a[16], float c, float s, int lane) {
    const float sg = ((lane >> LB) & 1) ? s : -s;
    const float nsg = -sg;
#pragma unroll
    for (int r = 0; r < 16; r += 2) {
        float p0 = shx(a[r],     1 << LB);
        float p1 = shx(a[r + 1], 1 << LB);
        float t0, t1;
        if (r & (1 << CB)) {          // CB >= 1 so pair is homogeneous
            mul2(t0, t1, p0, p1, c, c);
            fma2(t0, t1, a[r], a[r + 1], nsg, nsg, t0, t1);
        } else {
            mul2(t0, t1, a[r], a[r + 1], c, c);
            fma2(t0, t1, p0, p1, sg, sg, t0, t1);
        }
        a[r] = t0; a[r + 1] = t1;
    }
}

// ---- RY on reg bit BT with POST-CNOT(control = lane bit LC, target = same reg bit) fused ----
template<int BT, int LC>
__device__ __forceinline__ void ryr2_cx(float a[16], float c, float s, int lane) {
    const bool p = (lane >> LC) & 1;
    const float A = p ?  s : c;
    const float B = p ?  c : -s;
    const float C = p ?  c : s;
    const float D = p ? -s : c;
#pragma unroll
    for (int j = 0; j < 4; ++j) {
        const int k0 = 2 * j, k1 = 2 * j + 1;
        const int pp = ((k0 >> BT) << (BT + 1)) | (k0 & ((1 << BT) - 1));
        const int qq = ((k1 >> BT) << (BT + 1)) | (k1 & ((1 << BT) - 1));
        const int pm = pp | (1 << BT), qm = qq | (1 << BT);
        float l0, l1, h0, h1;
        mul2(l0, l1, a[pp], a[qq], A, A);
        fma2(l0, l1, a[pm], a[qm], B, B, l0, l1);
        mul2(h0, h1, a[pp], a[qq], C, C);
        fma2(h0, h1, a[pm], a[qm], D, D, h0, h1);
        a[pp] = l0; a[qq] = l1; a[pm] = h0; a[qm] = h1;
    }
}

// ---- CNOT: control reg bit BC, target lane bit LT (8 shuffles) ----
template<int BC, int LT>
__device__ __forceinline__ void crl(float a[16]) {
#pragma unroll
    for (int r = 0; r < 16; ++r) {
        if (r & (1 << BC)) a[r] = shx(a[r], 1 << LT);
    }
}

// ======= CRX gates (scalar): [[c, -i s],[-i s, c]] on control==1 subspace =======
template<int LC, int BT>
__device__ __forceinline__ void crx_lr_r2c(float ar[16], float ai[16], float c, float s, int lane) {
    const bool p = (lane >> LC) & 1;
    const float ce  = p ? c  : 1.0f;
    const float nse = p ? -s : 0.0f;
#pragma unroll
    for (int r = 0; r < 16; ++r) {
        if (!(r & (1 << BT))) {
            const int r1 = r | (1 << BT);
            ai[r]  = nse * ar[r1];
            ai[r1] = nse * ar[r];
            ar[r]  = ce * ar[r];
            ar[r1] = ce * ar[r1];
        }
    }
}

template<int LC, int BT>
__device__ __forceinline__ void crx_lr(float ar[16], float ai[16], float c, float s, int lane) {
    const bool p = (lane >> LC) & 1;
    const float ce = p ? c : 1.0f;
    const float se = p ? s : 0.0f;
#pragma unroll
    for (int r = 0; r < 16; ++r) {
        if (!(r & (1 << BT))) {
            const int r1 = r | (1 << BT);
            float a0r = ar[r], a0i = ai[r], a1r = ar[r1], a1i = ai[r1];
            ar[r]  = fmaf( se, a1i, ce * a0r);
            ai[r]  = fmaf(-se, a1r, ce * a0i);
            ar[r1] = fmaf( se, a0i, ce * a1r);
            ai[r1] = fmaf(-se, a0r, ce * a1i);
        }
    }
}

template<int BC, int LT>
__device__ __forceinline__ void crx_rl(float ar[16], float ai[16], float c, float s) {
#pragma unroll
    for (int r = 0; r < 16; ++r) {
        if (r & (1 << BC)) {
            float pr = shx(ar[r], 1 << LT);
            float pi = shx(ai[r], 1 << LT);
            float nr = fmaf( s, pi, c * ar[r]);
            float ni = fmaf(-s, pr, c * ai[r]);
            ar[r] = nr; ai[r] = ni;
        }
    }
}

template<int BC, int BT>
__device__ __forceinline__ void crx_rr(float ar[16], float ai[16], float c, float s) {
#pragma unroll
    for (int r = 0; r < 16; ++r) {
        if ((r & (1 << BC)) && !(r & (1 << BT))) {
            const int r1 = r | (1 << BT);
            float a0r = ar[r], a0i = ai[r], a1r = ar[r1], a1i = ai[r1];
            ar[r]  = fmaf( s, a1i, c * a0r);
            ai[r]  = fmaf(-s, a1r, c * a0i);
            ar[r1] = fmaf( s, a0i, c * a1r);
            ai[r1] = fmaf(-s, a0r, c * a1i);
        }
    }
}

// ---- middle Ry(theta) of the U3 decomposition: REAL rotation on a reg bit ----
template<int BT>
__device__ __forceinline__ void ry_creg(float ar[16], float ai[16], float ct, float st) {
#pragma unroll
    for (int r = 0; r < 16; ++r) {
        if (!(r & (1 << BT))) {
            const int r1 = r | (1 << BT);
            float a0r = ar[r], a0i = ai[r], a1r = ar[r1], a1i = ai[r1];
            ar[r]  = fmaf(-st, a1r, ct * a0r);
            ai[r]  = fmaf(-st, a1i, ct * a0i);
            ar[r1] = fmaf( st, a0r, ct * a1r);
            ai[r1] = fmaf( st, a0i, ct * a1i);
        }
    }
}

// ---- diagonal (⊗ Rz'(ang) over the 4 reg bits), centered: phase e^{i*ang*(popcount(r)-2)} ----
// (zr,zi) = e^{i ang}, (z2r,z2i) = e^{2i ang}. pc==2 amplitudes (6 of 16) are free.
__device__ __forceinline__ void rz4_layer(float ar[16], float ai[16],
                                          float zr, float zi, float z2r, float z2i) {
#pragma unroll
    for (int r = 0; r < 16; ++r) {
        const int pc = ((r) & 1) + ((r >> 1) & 1) + ((r >> 2) & 1) + ((r >> 3) & 1);
        if (pc == 2) continue;
        float pr, pi;
        if      (pc == 0) { pr = z2r; pi = -z2i; }
        else if (pc == 1) { pr = zr;  pi = -zi;  }
        else if (pc == 3) { pr = zr;  pi =  zi;  }
        else              { pr = z2r; pi =  z2i; }
        float re = ar[r], im = ai[r];
        ar[r] = fmaf(-pi, im, pr * re);
        ai[r] = fmaf( pi, re, pr * im);
    }
}

__device__ __forceinline__ void u3_coeffs(const float* __restrict__ p3,
    float& u00r, float& u01r, float& u01i,
    float& u10r, float& u10i, float& u11r, float& u11i) {
    const float th = p3[0], ph = p3[1], lm = p3[2];
    float st, ct;   __sincosf(0.5f * th, &st, &ct);
    float sl, cl;   __sincosf(lm, &sl, &cl);
    float sp, cp;   __sincosf(ph, &sp, &cp);
    float spl, cpl; __sincosf(ph + lm, &spl, &cpl);
    u00r = ct;
    u01r = -cl * st;  u01i = -sl * st;
    u10r =  cp * st;  u10i =  sp * st;
    u11r = cpl * ct;  u11i = spl * ct;
}

// ==================================================================================
__global__ void __launch_bounds__(256, 4) qcnn_kernel(
    const float* __restrict__ x,
    const float* __restrict__ crx_theta,
    const float* __restrict__ u3p,
    const float* __restrict__ w1,
    const float* __restrict__ b1,
    const float* __restrict__ w2,
    const float* __restrict__ b2,
    float* __restrict__ out, int nB)
{
    const int warp = (blockIdx.x * blockDim.x + threadIdx.x) >> 5;
    if (2 * warp >= nB) return;
    const int lane = threadIdx.x & 31;
    const int hl = lane >> 4;
    const int e  = 2 * warp + hl;
    const int el = (e < nB) ? e : (nB - 1);
    const int sl = lane & 15;

    // ---- per-element RY angles: lane-parallel sincos + broadcast ----
    // lane computes sincos of ONE angle (q = sl & 7), then all 8 are shfl-broadcast.
    float c8[8], s8[8];
    {
        float myS, myC;
        __sincosf(0.5f * x[el * 8 + (sl & 7)], &myS, &myC);
        const int base = lane & 16;   // element's lane-group base
#pragma unroll
        for (int q = 0; q < 8; ++q) {
            c8[q] = __shfl_sync(FULLMASK, myC, base + q);
            s8[q] = __shfl_sync(FULLMASK, myS, base + q);
        }
    }

    // ---- cycle 1: RY layer on |0..0> + CNOT ring (minus (q7,q0)) in closed form ----
    float a[16];
    {
        const bool L3 = sl & 8, L2 = sl & 4, L1 = sl & 2, L0 = sl & 1;
        const float P0  = L3 ? s8[0] : c8[0];
        const float w3a = (L3 ? s8[1] : c8[1]) * (L2 ? s8[2] : c8[2]);   // R3 = 0
        const float w3b = (L3 ? c8[1] : s8[1]) * (L2 ? c8[2] : s8[2]);   // R3 = 1
        const float w2a = (L2 ? s8[3] : c8[3]) * (L1 ? s8[4] : c8[4]);
        const float w2b = (L2 ? c8[3] : s8[3]) * (L1 ? c8[4] : s8[4]);
        const float w1a = (L1 ? s8[5] : c8[5]) * (L0 ? s8[6] : c8[6]);
        const float w1b = (L1 ? c8[5] : s8[5]) * (L0 ? c8[6] : s8[6]);
        const float w0a = L0 ? s8[7] : c8[7];
        const float w0b = L0 ? c8[7] : s8[7];
        const float A0 = P0 * w3a, A1 = P0 * w3b;
        const float B00 = A0 * w2a, B01 = A0 * w2b, B10 = A1 * w2a, B11 = A1 * w2b;
        const float C0 = B00 * w1a, C1 = B00 * w1b, C2 = B01 * w1a, C3 = B01 * w1b;
        const float C4 = B10 * w1a, C5 = B10 * w1b, C6 = B11 * w1a, C7 = B11 * w1b;
        a[0]  = C0 * w0a;  a[1]  = C0 * w0b;  a[2]  = C1 * w0a;  a[3]  = C1 * w0b;
        a[4]  = C2 * w0a;  a[5]  = C2 * w0b;  a[6]  = C3 * w0a;  a[7]  = C3 * w0b;
        a[8]  = C4 * w0a;  a[9]  = C4 * w0b;  a[10] = C5 * w0a;  a[11] = C5 * w0b;
        a[12] = C6 * w0a;  a[13] = C6 * w0b;  a[14] = C7 * w0a;  a[15] = C7 * w0b;
    }

    // ---- cycles 2..4: RY layer with all ring CNOTs fused in ----
#pragma unroll 1
    for (int cyc = 0; cyc < 3; ++cyc) {
        ryl2_cx<3>(a, c8[0], s8[0], lane);       // RY q0, pre-CX(7,0) ctrl R0
        ryr2_cx<3, 3>(a, c8[1], s8[1], lane);    // RY q1 (R3), post-CX ctrl q0 (L3)
        ryl2_post<2, 3>(a, c8[2], s8[2], lane);  // RY q2 (L2), post-CX ctrl q1 (R3)
        ryr2_cx<2, 2>(a, c8[3], s8[3], lane);    // RY q3 (R2), post-CX ctrl q2 (L2)
        ryl2_post<1, 2>(a, c8[4], s8[4], lane);  // RY q4 (L1), post-CX ctrl q3 (R2)
        ryr2_cx<1, 1>(a, c8[5], s8[5], lane);    // RY q5 (R1), post-CX ctrl q4 (L1)
        ryl2_post<0, 1>(a, c8[6], s8[6], lane);  // RY q6 (L0), post-CX ctrl q5 (R1)
        ryr2_cx<0, 0>(a, c8[7], s8[7], lane);    // RY q7 (R0), post-CX ctrl q6 (L0)
    }
    crl<0, 3>(a);                                // final pending CX(7,0)

    // ================= final (complex) stage, scalar =================
    float* ar = a;
    float ai[16];

    // ---- layer 0 CRX ----
    {
        float s0, c0;
        __sincosf(0.5f * crx_theta[0], &s0, &c0);
        crx_lr_r2c<3, 3>(ar, ai, c0, s0, lane);  // (q0,q1) real -> complex
        crx_lr<2, 2>(ar, ai, c0, s0, lane);      // (q2,q3)
        crx_lr<1, 1>(ar, ai, c0, s0, lane);      // (q4,q5)
        crx_lr<0, 0>(ar, ai, c0, s0, lane);      // (q6,q7)
        crx_rl<3, 2>(ar, ai, c0, s0);            // (q1,q2)
        crx_rl<2, 1>(ar, ai, c0, s0);            // (q3,q4)
        crx_rl<1, 0>(ar, ai, c0, s0);            // (q5,q6)
    }

    // ---- layer 0 U3 on [1,3,5,7] via exact decomposition U3 = Rz'(phi) Ry(th) Rz'(lm) ----
    // (centered diagonal phases; residual global phase cancels in the measurement)
    {
        float sth, cth;  __sincosf(0.5f * u3p[0], &sth, &cth);
        float slm, clm;  __sincosf(u3p[2], &slm, &clm);
        float sph, cph;  __sincosf(u3p[1], &sph, &cph);
        const float zl2r = fmaf(clm, clm, -slm * slm), zl2i = 2.0f * clm * slm;
        const float zp2r = fmaf(cph, cph, -sph * sph), zp2i = 2.0f * cph * sph;

        rz4_layer(ar, ai, clm, slm, zl2r, zl2i);   // D(lambda)
        ry_creg<3>(ar, ai, cth, sth);              // Ry on q1
        ry_creg<2>(ar, ai, cth, sth);              // Ry on q3
        ry_creg<1>(ar, ai, cth, sth);              // Ry on q5
        ry_creg<0>(ar, ai, cth, sth);              // Ry on q7
        rz4_layer(ar, ai, cph, sph, zp2r, zp2i);   // D(phi)
    }

    // ---- layer 1 CRX on [1,3,5,7]: (1,3)(5,7) then (3,5) — register-local ----
    {
        float s1, c1;
        __sincosf(0.5f * crx_theta[1], &s1, &c1);
        crx_rr<3, 2>(ar, ai, c1, s1);    // (q1,q3)
        crx_rr<1, 0>(ar, ai, c1, s1);    // (q5,q7)
        crx_rr<2, 1>(ar, ai, c1, s1);    // (q3,q5)
    }

    // ---- layer 1 U3 on q3,q7 folded into the measurement:
    //      <Z after U3> = <M> with M = U† Z U = [[aM, b],[conj(b), -aM]].
    float aM, bMr, bMi;
    {
        float u00r,u01r,u01i,u10r,u10i,u11r,u11i;
        u3_coeffs(u3p + 3, u00r,u01r,u01i,u10r,u10i,u11r,u11i);
        aM  = u00r * u00r - (u10r * u10r + u10i * u10i);
        bMr = 2.0f * (u00r * u01r - (u10r * u11r + u10i * u11i));
        bMi = 2.0f * (u00r * u01i - (u10r * u11i - u10i * u11r));
    }
    // f0 = <M on q3> (reg bit 2), f1 = <M on q7> (reg bit 0).
    float f0 = 0.0f, f1 = 0.0f;
#pragma unroll
    for (int qd = 0; qd < 4; ++qd) {
        const int r = ((qd >> 1) << 3) | ((qd & 1) << 1);   // 0, 2, 8, 10
        const int rA = r, rB = r | 1, rC = r | 4, rD = r | 5;
        const float mA = fmaf(ar[rA], ar[rA], ai[rA] * ai[rA]);
        const float mB = fmaf(ar[rB], ar[rB], ai[rB] * ai[rB]);
        const float mC = fmaf(ar[rC], ar[rC], ai[rC] * ai[rC]);
        const float mD = fmaf(ar[rD], ar[rD], ai[rD] * ai[rD]);
        // f0 pairs: (A,C), (B,D)
        {
            float wre = fmaf(ai[rA], ai[rC], ar[rA] * ar[rC]);
            float wim = fmaf(-ai[rA], ar[rC], ar[rA] * ai[rC]);
            f0 = fmaf(aM, mA - mC, f0);
            f0 = fmaf(bMr, wre, f0);
            f0 = fmaf(-bMi, wim, f0);
            wre = fmaf(ai[rB], ai[rD], ar[rB] * ar[rD]);
            wim = fmaf(-ai[rB], ar[rD], ar[rB] * ai[rD]);
            f0 = fmaf(aM, mB - mD, f0);
            f0 = fmaf(bMr, wre, f0);
            f0 = fmaf(-bMi, wim, f0);
        }
        // f1 pairs: (A,B), (C,D)
        {
            float wre = fmaf(ai[rA], ai[rB], ar[rA] * ar[rB]);
            float wim = fmaf(-ai[rA], ar[rB], ar[rA] * ai[rB]);
            f1 = fmaf(aM, mA - mB, f1);
            f1 = fmaf(bMr, wre, f1);
            f1 = fmaf(-bMi, wim, f1);
            wre = fmaf(ai[rC], ai[rD], ar[rC] * ar[rD]);
            wim = fmaf(-ai[rC], ar[rD], ar[rC] * ai[rD]);
            f1 = fmaf(aM, mC - mD, f1);
            f1 = fmaf(bMr, wre, f1);
            f1 = fmaf(-bMi, wim, f1);
        }
    }
#pragma unroll
    for (int m = 8; m >= 1; m >>= 1) {   // stays within half-warp
        f0 += shx(f0, m);
        f1 += shx(f1, m);
    }

    // ---- MLP head: sigmoid(tanh(f @ w1 + b1) @ w2 + b2), tanh spread over 10 lanes ----
    float contrib = 0.0f;
    if (sl < 10) {
        float h = tanhf(fmaf(f0, w1[sl], fmaf(f1, w1[10 + sl], b1[sl])));
        contrib = h * w2[sl];
    }
#pragma unroll
    for (int m = 8; m >= 1; m >>= 1) contrib += shx(contrib, m);
    if (sl == 0 && e < nB) {
        out[e] = 1.0f / (1.0f + __expf(-(contrib + b2[0])));
    }
}

extern "C" void kernel_launch(void* const* d_in, const int* in_sizes, int n_in,
                              void* d_out, int out_size) {
    const float* x         = (const float*)d_in[0];
    const float* crx_theta = (const float*)d_in[1];
    const float* u3_params = (const float*)d_in[2];
    const float* w1        = (const float*)d_in[3];
    const float* b1        = (const float*)d_in[4];
    const float* w2        = (const float*)d_in[5];
    const float* b2        = (const float*)d_in[6];
    float* out = (float*)d_out;

    const int nB = out_size;                  // (B, 1) output -> B batch elements
    const int threads = 256;                  // 8 warps/block, 2 elements per warp
    const int nWarps = (nB + 1) / 2;
    const int blocks = (nWarps * 32 + threads - 1) / threads;
    qcnn_kernel<<<blocks, threads>>>(x, crx_theta, u3_params, w1, b1, w2, b2, out, nB);
}

// round 14
// speedup vs baseline: 1.2078x; 1.0385x over previous
#include <cuda_runtime.h>

#define FULLMASK 0xffffffffu

__device__ __forceinline__ float shx(float v, int m) { return __shfl_xor_sync(FULLMASK, v, m); }

// Packed fp32x2 math (Blackwell FFMA2 path — only reachable via PTX f32x2).
// Only used where operand packs are NATURAL (no component swaps): encoding loop
// and the real Ry rotations of the U3 decomposition.
__device__ __forceinline__ void mul2(float& d0, float& d1, float a0, float a1,
                                     float b0, float b1) {
    asm("{\n\t.reg .b64 A,B,D;\n\t"
        "mov.b64 A, {%2,%3};\n\t"
        "mov.b64 B, {%4,%5};\n\t"
        "mul.rn.f32x2 D, A, B;\n\t"
        "mov.b64 {%0,%1}, D;\n\t}"
        : "=f"(d0), "=f"(d1) : "f"(a0), "f"(a1), "f"(b0), "f"(b1));
}
__device__ __forceinline__ void fma2(float& d0, float& d1, float a0, float a1,
                                     float b0, float b1, float c0, float c1) {
    asm("{\n\t.reg .b64 A,B,C,D;\n\t"
        "mov.b64 A, {%2,%3};\n\t"
        "mov.b64 B, {%4,%5};\n\t"
        "mov.b64 C, {%6,%7};\n\t"
        "fma.rn.f32x2 D, A, B, C;\n\t"
        "mov.b64 {%0,%1}, D;\n\t}"
        : "=f"(d0), "=f"(d1) : "f"(a0), "f"(a1), "f"(b0), "f"(b1), "f"(c0), "f"(c1));
}

// Uniform (batch-independent) gate coefficients, produced by qcnn_setup.
// [0]=c0 [1]=s0 | [2]=cth [3]=sth | [4]=clm [5]=slm [6]=zl2r [7]=zl2i
// [8]=cph [9]=sph [10]=zp2r [11]=zp2i | [12]=c1 [13]=s1 [14]=aM [15]=bMr
// [16]=bMi [17]=b2 [18],[19]=pad
__device__ __align__(16) float g_coef[20];

__global__ void qcnn_setup(const float* __restrict__ crx_theta,
                           const float* __restrict__ u3p,
                           const float* __restrict__ b2) {
    if (threadIdx.x != 0 || blockIdx.x != 0) return;
    float s0, c0;  __sincosf(0.5f * crx_theta[0], &s0, &c0);
    g_coef[0] = c0; g_coef[1] = s0;

    float sth, cth;  __sincosf(0.5f * u3p[0], &sth, &cth);
    float slm, clm;  __sincosf(u3p[2], &slm, &clm);
    float sph, cph;  __sincosf(u3p[1], &sph, &cph);
    g_coef[2] = cth; g_coef[3] = sth;
    g_coef[4] = clm; g_coef[5] = slm;
    g_coef[6] = fmaf(clm, clm, -slm * slm); g_coef[7] = 2.0f * clm * slm;
    g_coef[8] = cph; g_coef[9] = sph;
    g_coef[10] = fmaf(cph, cph, -sph * sph); g_coef[11] = 2.0f * cph * sph;

    float s1, c1;  __sincosf(0.5f * crx_theta[1], &s1, &c1);
    g_coef[12] = c1; g_coef[13] = s1;

    // measurement observable M = U3† Z U3 for layer-1 U3 (u3p[3..5])
    {
        const float th = u3p[3], ph = u3p[4], lm = u3p[5];
        float st2, ct2;   __sincosf(0.5f * th, &st2, &ct2);
        float sl2, cl2;   __sincosf(lm, &sl2, &cl2);
        float sp2, cp2;   __sincosf(ph, &sp2, &cp2);
        float spl, cpl;   __sincosf(ph + lm, &spl, &cpl);
        const float u00r = ct2;
        const float u01r = -cl2 * st2, u01i = -sl2 * st2;
        const float u10r =  cp2 * st2, u10i =  sp2 * st2;
        const float u11r =  cpl * ct2, u11i =  spl * ct2;
        g_coef[14] = u00r * u00r - (u10r * u10r + u10i * u10i);                  // aM
        g_coef[15] = 2.0f * (u00r * u01r - (u10r * u11r + u10i * u11i));         // bMr
        g_coef[16] = 2.0f * (u00r * u01i - (u10r * u11i - u10i * u11r));         // bMi
    }
    g_coef[17] = b2[0];
    g_coef[18] = 0.0f; g_coef[19] = 0.0f;
}

// Layout: HALF-WARP per batch element, 16 amplitudes per lane.
// sub-lane sl = lane & 15 (bits L3..L0), register index r (bits R3..R0).
// Qubit -> bit mapping (parity trick: odd qubits live in registers):
//   q0->L3  q2->L2  q4->L1  q6->L0     (lane bits)
//   q1->R3  q3->R2  q5->R1  q7->R0     (register bits)
// All shuffle masks <= 8 => shuffles never cross the half-warp boundary.

// ---- RY on lane bit LB with PRE-CNOT(control = reg bit 0) fused (ring-closing CX(7,0)) ----
template<int LB>
__device__ __forceinline__ void ryl2_cx(float a[16], float c, float s, int lane) {
    const float sg = ((lane >> LB) & 1) ? s : -s;
#pragma unroll
    for (int r = 0; r < 16; r += 2) {
        float p0 = shx(a[r],     1 << LB);   // r even: control clear
        float p1 = shx(a[r + 1], 1 << LB);   // r+1 odd: control set -> pre-swap own/partner
        float t0, t1;
        mul2(t0, t1, a[r], p1, c, c);
        fma2(t0, t1, p0, a[r + 1], sg, sg, t0, t1);
        a[r] = t0; a[r + 1] = t1;
    }
}

// ---- RY on lane bit LB with POST-CNOT(control = reg bit CB, target = same lane bit) fused ----
template<int LB, int CB>
__device__ __forceinline__ void ryl2_post(float a[16], float c, float s, int lane) {
    const float sg = ((lane >> LB) & 1) ? s : -s;
    const float nsg = -sg;
#pragma unroll
    for (int r = 0; r < 16; r += 2) {
        float p0 = shx(a[r],     1 << LB);
        float p1 = shx(a[r + 1], 1 << LB);
        float t0, t1;
        if (r & (1 << CB)) {          // CB >= 1 so pair is homogeneous
            mul2(t0, t1, p0, p1, c, c);
            fma2(t0, t1, a[r], a[r + 1], nsg, nsg, t0, t1);
        } else {
            mul2(t0, t1, a[r], a[r + 1], c, c);
            fma2(t0, t1, p0, p1, sg, sg, t0, t1);
        }
        a[r] = t0; a[r + 1] = t1;
    }
}

// ---- RY on reg bit BT with POST-CNOT(control = lane bit LC, target = same reg bit) fused ----
template<int BT, int LC>
__device__ __forceinline__ void ryr2_cx(float a[16], float c, float s, int lane) {
    const bool p = (lane >> LC) & 1;
    const float A = p ?  s : c;
    const float B = p ?  c : -s;
    const float C = p ?  c : s;
    const float D = p ? -s : c;
#pragma unroll
    for (int j = 0; j < 4; ++j) {
        const int k0 = 2 * j, k1 = 2 * j + 1;
        const int pp = ((k0 >> BT) << (BT + 1)) | (k0 & ((1 << BT) - 1));
        const int qq = ((k1 >> BT) << (BT + 1)) | (k1 & ((1 << BT) - 1));
        const int pm = pp | (1 << BT), qm = qq | (1 << BT);
        float l0, l1, h0, h1;
        mul2(l0, l1, a[pp], a[qq], A, A);
        fma2(l0, l1, a[pm], a[qm], B, B, l0, l1);
        mul2(h0, h1, a[pp], a[qq], C, C);
        fma2(h0, h1, a[pm], a[qm], D, D, h0, h1);
        a[pp] = l0; a[qq] = l1; a[pm] = h0; a[qm] = h1;
    }
}

// ---- CNOT: control reg bit BC, target lane bit LT (8 shuffles) ----
template<int BC, int LT>
__device__ __forceinline__ void crl(float a[16]) {
#pragma unroll
    for (int r = 0; r < 16; ++r) {
        if (r & (1 << BC)) a[r] = shx(a[r], 1 << LT);
    }
}

// ======= CRX gates (scalar): [[c, -i s],[-i s, c]] on control==1 subspace =======
template<int LC, int BT>
__device__ __forceinline__ void crx_lr_r2c(float ar[16], float ai[16], float c, float s, int lane) {
    const bool p = (lane >> LC) & 1;
    const float ce  = p ? c  : 1.0f;
    const float nse = p ? -s : 0.0f;
#pragma unroll
    for (int r = 0; r < 16; ++r) {
        if (!(r & (1 << BT))) {
            const int r1 = r | (1 << BT);
            ai[r]  = nse * ar[r1];
            ai[r1] = nse * ar[r];
            ar[r]  = ce * ar[r];
            ar[r1] = ce * ar[r1];
        }
    }
}

template<int LC, int BT>
__device__ __forceinline__ void crx_lr(float ar[16], float ai[16], float c, float s, int lane) {
    const bool p = (lane >> LC) & 1;
    const float ce = p ? c : 1.0f;
    const float se = p ? s : 0.0f;
#pragma unroll
    for (int r = 0; r < 16; ++r) {
        if (!(r & (1 << BT))) {
            const int r1 = r | (1 << BT);
            float a0r = ar[r], a0i = ai[r], a1r = ar[r1], a1i = ai[r1];
            ar[r]  = fmaf( se, a1i, ce * a0r);
            ai[r]  = fmaf(-se, a1r, ce * a0i);
            ar[r1] = fmaf( se, a0i, ce * a1r);
            ai[r1] = fmaf(-se, a0r, ce * a1i);
        }
    }
}

template<int BC, int LT>
__device__ __forceinline__ void crx_rl(float ar[16], float ai[16], float c, float s) {
#pragma unroll
    for (int r = 0; r < 16; ++r) {
        if (r & (1 << BC)) {
            float pr = shx(ar[r], 1 << LT);
            float pi = shx(ai[r], 1 << LT);
            float nr = fmaf( s, pi, c * ar[r]);
            float ni = fmaf(-s, pr, c * ai[r]);
            ar[r] = nr; ai[r] = ni;
        }
    }
}

template<int BC, int BT>
__device__ __forceinline__ void crx_rr(float ar[16], float ai[16], float c, float s) {
#pragma unroll
    for (int r = 0; r < 16; ++r) {
        if ((r & (1 << BC)) && !(r & (1 << BT))) {
            const int r1 = r | (1 << BT);
            float a0r = ar[r], a0i = ai[r], a1r = ar[r1], a1i = ai[r1];
            ar[r]  = fmaf( s, a1i, c * a0r);
            ai[r]  = fmaf(-s, a1r, c * a0i);
            ar[r1] = fmaf( s, a0i, c * a1r);
            ai[r1] = fmaf(-s, a0r, c * a1i);
        }
    }
}

// ---- middle Ry(theta) of the U3 decomposition: REAL rotation on a reg bit.
// Packed f32x2 with NATURAL (non-swapped) (re,im) pairs: new0 = ct*z0 - st*z1,
// new1 = st*z0 + ct*z1, componentwise identical coefficients.
template<int BT>
__device__ __forceinline__ void ry_creg2(float ar[16], float ai[16], float ct, float st) {
    const float nst = -st;
#pragma unroll
    for (int r = 0; r < 16; ++r) {
        if (!(r & (1 << BT))) {
            const int r1 = r | (1 << BT);
            float t0, t1, u0, u1;
            mul2(t0, t1, ar[r], ai[r], ct, ct);
            fma2(t0, t1, ar[r1], ai[r1], nst, nst, t0, t1);
            mul2(u0, u1, ar[r], ai[r], st, st);
            fma2(u0, u1, ar[r1], ai[r1], ct, ct, u0, u1);
            ar[r] = t0; ai[r] = t1; ar[r1] = u0; ai[r1] = u1;
        }
    }
}

// ---- diagonal (⊗ Rz'(ang) over the 4 reg bits), centered: phase e^{i*ang*(popcount(r)-2)} ----
__device__ __forceinline__ void rz4_layer(float ar[16], float ai[16],
                                          float zr, float zi, float z2r, float z2i) {
#pragma unroll
    for (int r = 0; r < 16; ++r) {
        const int pc = ((r) & 1) + ((r >> 1) & 1) + ((r >> 2) & 1) + ((r >> 3) & 1);
        if (pc == 2) continue;
        float pr, pi;
        if      (pc == 0) { pr = z2r; pi = -z2i; }
        else if (pc == 1) { pr = zr;  pi = -zi;  }
        else if (pc == 3) { pr = zr;  pi =  zi;  }
        else              { pr = z2r; pi =  z2i; }
        float re = ar[r], im = ai[r];
        ar[r] = fmaf(-pi, im, pr * re);
        ai[r] = fmaf( pi, re, pr * im);
    }
}

// ==================================================================================
__global__ void __launch_bounds__(256, 4) qcnn_kernel(
    const float* __restrict__ x,
    const float* __restrict__ w1,
    const float* __restrict__ b1,
    const float* __restrict__ w2,
    float* __restrict__ out, int nB)
{
    const int warp = (blockIdx.x * blockDim.x + threadIdx.x) >> 5;
    if (2 * warp >= nB) return;
    const int lane = threadIdx.x & 31;
    const int hl = lane >> 4;
    const int e  = 2 * warp + hl;
    const int el = (e < nB) ? e : (nB - 1);
    const int sl = lane & 15;

    // ---- per-element RY angles: lane-parallel sincos + broadcast ----
    float c8[8], s8[8];
    {
        float myS, myC;
        __sincosf(0.5f * x[el * 8 + (sl & 7)], &myS, &myC);
        const int base = lane & 16;   // element's lane-group base
#pragma unroll
        for (int q = 0; q < 8; ++q) {
            c8[q] = __shfl_sync(FULLMASK, myC, base + q);
            s8[q] = __shfl_sync(FULLMASK, myS, base + q);
        }
    }

    // ---- cycle 1: RY layer on |0..0> + CNOT ring (minus (q7,q0)) in closed form ----
    float a[16];
    {
        const bool L3 = sl & 8, L2 = sl & 4, L1 = sl & 2, L0 = sl & 1;
        const float P0  = L3 ? s8[0] : c8[0];
        const float w3a = (L3 ? s8[1] : c8[1]) * (L2 ? s8[2] : c8[2]);   // R3 = 0
        const float w3b = (L3 ? c8[1] : s8[1]) * (L2 ? c8[2] : s8[2]);   // R3 = 1
        const float w2a = (L2 ? s8[3] : c8[3]) * (L1 ? s8[4] : c8[4]);
        const float w2b = (L2 ? c8[3] : s8[3]) * (L1 ? c8[4] : s8[4]);
        const float w1a = (L1 ? s8[5] : c8[5]) * (L0 ? s8[6] : c8[6]);
        const float w1b = (L1 ? c8[5] : s8[5]) * (L0 ? c8[6] : s8[6]);
        const float w0a = L0 ? s8[7] : c8[7];
        const float w0b = L0 ? c8[7] : s8[7];
        const float A0 = P0 * w3a, A1 = P0 * w3b;
        const float B00 = A0 * w2a, B01 = A0 * w2b, B10 = A1 * w2a, B11 = A1 * w2b;
        const float C0 = B00 * w1a, C1 = B00 * w1b, C2 = B01 * w1a, C3 = B01 * w1b;
        const float C4 = B10 * w1a, C5 = B10 * w1b, C6 = B11 * w1a, C7 = B11 * w1b;
        a[0]  = C0 * w0a;  a[1]  = C0 * w0b;  a[2]  = C1 * w0a;  a[3]  = C1 * w0b;
        a[4]  = C2 * w0a;  a[5]  = C2 * w0b;  a[6]  = C3 * w0a;  a[7]  = C3 * w0b;
        a[8]  = C4 * w0a;  a[9]  = C4 * w0b;  a[10] = C5 * w0a;  a[11] = C5 * w0b;
        a[12] = C6 * w0a;  a[13] = C6 * w0b;  a[14] = C7 * w0a;  a[15] = C7 * w0b;
    }

    // ---- cycles 2..4: RY layer with all ring CNOTs fused in ----
#pragma unroll 1
    for (int cyc = 0; cyc < 3; ++cyc) {
        ryl2_cx<3>(a, c8[0], s8[0], lane);       // RY q0, pre-CX(7,0) ctrl R0
        ryr2_cx<3, 3>(a, c8[1], s8[1], lane);    // RY q1 (R3), post-CX ctrl q0 (L3)
        ryl2_post<2, 3>(a, c8[2], s8[2], lane);  // RY q2 (L2), post-CX ctrl q1 (R3)
        ryr2_cx<2, 2>(a, c8[3], s8[3], lane);    // RY q3 (R2), post-CX ctrl q2 (L2)
        ryl2_post<1, 2>(a, c8[4], s8[4], lane);  // RY q4 (L1), post-CX ctrl q3 (R2)
        ryr2_cx<1, 1>(a, c8[5], s8[5], lane);    // RY q5 (R1), post-CX ctrl q4 (L1)
        ryl2_post<0, 1>(a, c8[6], s8[6], lane);  // RY q6 (L0), post-CX ctrl q5 (R1)
        ryr2_cx<0, 0>(a, c8[7], s8[7], lane);    // RY q7 (R0), post-CX ctrl q6 (L0)
    }
    crl<0, 3>(a);                                // final pending CX(7,0)

    // ================= final (complex) stage =================
    float* ar = a;
    float ai[16];

    // ---- layer 0 CRX (coefficients precomputed in g_coef) ----
    {
        const float4 k0 = *reinterpret_cast<const float4*>(&g_coef[0]);  // c0,s0,cth,sth
        const float c0 = k0.x, s0 = k0.y;
        crx_lr_r2c<3, 3>(ar, ai, c0, s0, lane);  // (q0,q1) real -> complex
        crx_lr<2, 2>(ar, ai, c0, s0, lane);      // (q2,q3)
        crx_lr<1, 1>(ar, ai, c0, s0, lane);      // (q4,q5)
        crx_lr<0, 0>(ar, ai, c0, s0, lane);      // (q6,q7)
        crx_rl<3, 2>(ar, ai, c0, s0);            // (q1,q2)
        crx_rl<2, 1>(ar, ai, c0, s0);            // (q3,q4)
        crx_rl<1, 0>(ar, ai, c0, s0);            // (q5,q6)

        // ---- layer 0 U3 on [1,3,5,7]: Rz'(phi) Ry(th) Rz'(lm), phases centered ----
        const float cth = k0.z, sth = k0.w;
        {
            const float4 kl = *reinterpret_cast<const float4*>(&g_coef[4]);  // clm,slm,zl2r,zl2i
            rz4_layer(ar, ai, kl.x, kl.y, kl.z, kl.w);   // D(lambda)
        }
        ry_creg2<3>(ar, ai, cth, sth);               // Ry on q1
        ry_creg2<2>(ar, ai, cth, sth);               // Ry on q3
        ry_creg2<1>(ar, ai, cth, sth);               // Ry on q5
        ry_creg2<0>(ar, ai, cth, sth);               // Ry on q7
        {
            const float4 kp = *reinterpret_cast<const float4*>(&g_coef[8]);  // cph,sph,zp2r,zp2i
            rz4_layer(ar, ai, kp.x, kp.y, kp.z, kp.w);   // D(phi)
        }
    }

    // ---- layer 1 CRX on [1,3,5,7]: (1,3)(5,7) then (3,5) — register-local ----
    const float4 k3 = *reinterpret_cast<const float4*>(&g_coef[12]);   // c1,s1,aM,bMr
    {
        const float c1 = k3.x, s1 = k3.y;
        crx_rr<3, 2>(ar, ai, c1, s1);    // (q1,q3)
        crx_rr<1, 0>(ar, ai, c1, s1);    // (q5,q7)
        crx_rr<2, 1>(ar, ai, c1, s1);    // (q3,q5)
    }

    // ---- measurement with layer-1 U3 folded in: M = [[aM, b],[conj(b), -aM]] ----
    const float aM = k3.z, bMr = k3.w;
    const float2 k4 = *reinterpret_cast<const float2*>(&g_coef[16]);   // bMi, b2
    const float bMi = k4.x;
    // f0 = <M on q3> (reg bit 2), f1 = <M on q7> (reg bit 0).
    float f0 = 0.0f, f1 = 0.0f;
#pragma unroll
    for (int qd = 0; qd < 4; ++qd) {
        const int r = ((qd >> 1) << 3) | ((qd & 1) << 1);   // 0, 2, 8, 10
        const int rA = r, rB = r | 1, rC = r | 4, rD = r | 5;
        const float mA = fmaf(ar[rA], ar[rA], ai[rA] * ai[rA]);
        const float mB = fmaf(ar[rB], ar[rB], ai[rB] * ai[rB]);
        const float mC = fmaf(ar[rC], ar[rC], ai[rC] * ai[rC]);
        const float mD = fmaf(ar[rD], ar[rD], ai[rD] * ai[rD]);
        // f0 pairs: (A,C), (B,D)
        {
            float wre = fmaf(ai[rA], ai[rC], ar[rA] * ar[rC]);
            float wim = fmaf(-ai[rA], ar[rC], ar[rA] * ai[rC]);
            f0 = fmaf(aM, mA - mC, f0);
            f0 = fmaf(bMr, wre, f0);
            f0 = fmaf(-bMi, wim, f0);
            wre = fmaf(ai[rB], ai[rD], ar[rB] * ar[rD]);
            wim = fmaf(-ai[rB], ar[rD], ar[rB] * ai[rD]);
            f0 = fmaf(aM, mB - mD, f0);
            f0 = fmaf(bMr, wre, f0);
            f0 = fmaf(-bMi, wim, f0);
        }
        // f1 pairs: (A,B), (C,D)
        {
            float wre = fmaf(ai[rA], ai[rB], ar[rA] * ar[rB]);
            float wim = fmaf(-ai[rA], ar[rB], ar[rA] * ai[rB]);
            f1 = fmaf(aM, mA - mB, f1);
            f1 = fmaf(bMr, wre, f1);
            f1 = fmaf(-bMi, wim, f1);
            wre = fmaf(ai[rC], ai[rD], ar[rC] * ar[rD]);
            wim = fmaf(-ai[rC], ar[rD], ar[rC] * ai[rD]);
            f1 = fmaf(aM, mC - mD, f1);
            f1 = fmaf(bMr, wre, f1);
            f1 = fmaf(-bMi, wim, f1);
        }
    }
#pragma unroll
    for (int m = 8; m >= 1; m >>= 1) {   // stays within half-warp
        f0 += shx(f0, m);
        f1 += shx(f1, m);
    }

    // ---- MLP head: sigmoid(tanh(f @ w1 + b1) @ w2 + b2), tanh spread over 10 lanes ----
    float contrib = 0.0f;
    if (sl < 10) {
        float h = tanhf(fmaf(f0, w1[sl], fmaf(f1, w1[10 + sl], b1[sl])));
        contrib = h * w2[sl];
    }
#pragma unroll
    for (int m = 8; m >= 1; m >>= 1) contrib += shx(contrib, m);
    if (sl == 0 && e < nB) {
        out[e] = 1.0f / (1.0f + __expf(-(contrib + k4.y)));
    }
}

extern "C" void kernel_launch(void* const* d_in, const int* in_sizes, int n_in,
                              void* d_out, int out_size) {
    const float* x         = (const float*)d_in[0];
    const float* crx_theta = (const float*)d_in[1];
    const float* u3_params = (const float*)d_in[2];
    const float* w1        = (const float*)d_in[3];
    const float* b1        = (const float*)d_in[4];
    const float* w2        = (const float*)d_in[5];
    const float* b2        = (const float*)d_in[6];
    float* out = (float*)d_out;

    const int nB = out_size;                  // (B, 1) output -> B batch elements

    qcnn_setup<<<1, 32>>>(crx_theta, u3_params, b2);

    const int threads = 256;                  // 8 warps/block, 2 elements per warp
    const int nWarps = (nB + 1) / 2;
    const int blocks = (nWarps * 32 + threads - 1) / threads;
    qcnn_kernel<<<blocks, threads>>>(x, w1, b1, w2, out, nB);
}